// round 7
// baseline (speedup 1.0000x reference)
#include <cuda_runtime.h>
#include <cuda_bf16.h>
#include <cstdint>

#define N_NODES 100000
#define N_EDGES 800000
#define DIM 128
#define NTILES ((N_NODES + 127) / 128)
#define NB 98              // scan blocks: ceil(100000/1024)

// ---------------------------------------------------------------------------
// Scratch (allocation-free rule: __device__ globals)
// ---------------------------------------------------------------------------
__device__ float g_v[N_NODES * DIM];
__device__ float g_h[N_NODES * DIM];
__device__ unsigned short g_Wmma[4][2 * 128 * 128];  // prepacked W images
// CSR-by-dst build
__device__ int g_cnt[N_NODES];     // degree histogram
__device__ int g_start[N_NODES];   // row start (immutable)
__device__ int g_cur[N_NODES];     // fill cursor (mutated by bin)
__device__ int g_bsum[NB];         // scan partials
__device__ int g_ebuf[N_EDGES];    // src ids grouped by dst

// swizzled byte offset of (row, 16B-chunk kc) in a 256B-row tile
#define SW_OFF(row, kc) ((uint32_t)(row) * 256u + ((uint32_t)(((kc) ^ ((row) & 7))) << 4))

__device__ __forceinline__ uint32_t smem_u32(const void* p) {
    uint32_t a;
    asm("{ .reg .u64 t; cvta.to.shared.u64 t, %1; cvt.u32.u64 %0, t; }"
        : "=r"(a) : "l"(p));
    return a;
}
__device__ __forceinline__ void ldsm_x4(uint32_t& r0, uint32_t& r1, uint32_t& r2,
                                        uint32_t& r3, uint32_t addr) {
    asm volatile("ldmatrix.sync.aligned.m8n8.x4.shared.b16 {%0,%1,%2,%3}, [%4];"
                 : "=r"(r0), "=r"(r1), "=r"(r2), "=r"(r3) : "r"(addr));
}
__device__ __forceinline__ void mma_bf16(float* d, const uint32_t* a, const uint32_t* b) {
    asm volatile(
        "mma.sync.aligned.m16n8k16.row.col.f32.bf16.bf16.f32 "
        "{%0,%1,%2,%3}, {%4,%5,%6,%7}, {%8,%9}, {%0,%1,%2,%3};"
        : "+f"(d[0]), "+f"(d[1]), "+f"(d[2]), "+f"(d[3])
        : "r"(a[0]), "r"(a[1]), "r"(a[2]), "r"(a[3]), "r"(b[0]), "r"(b[1]));
}

// ---------------------------------------------------------------------------
// Prepack W -> g_Wmma: bf16 hi/lo, [n][k] rows (256B), XOR-swizzled 16B chunks
// ---------------------------------------------------------------------------
__global__ __launch_bounds__(256) void prepack_kernel(
    const float* __restrict__ W_v, const float* __restrict__ W_a)
{
    const int idx = blockIdx.x * 256 + threadIdx.x;
    if (idx >= 4 * 2 * 128 * 128) return;
    const int tile = idx >> 15;
    const int seg  = (idx >> 14) & 1;
    const int rem  = idx & 16383;
    const int n    = rem >> 7;
    const int k    = rem & 127;
    const int mat  = tile >> 1;
    const int typ  = tile & 1;

    const float* Wp = (mat ? W_a : W_v) + typ * DIM * DIM;
    const float w = Wp[k * DIM + n];
    __nv_bfloat16 hi = __float2bfloat16_rn(w);
    unsigned short out;
    if (seg == 0) {
        out = *(unsigned short*)&hi;
    } else {
        __nv_bfloat16 lo = __float2bfloat16_rn(w - __bfloat162float(hi));
        out = *(unsigned short*)&lo;
    }
    const uint32_t boff = SW_OFF(n, k >> 3) + (k & 7) * 2;
    g_Wmma[tile][seg * 16384 + (boff >> 1)] = out;
}

// ---------------------------------------------------------------------------
// CSR build: zero -> histogram -> 3-step exclusive scan -> bin
// ---------------------------------------------------------------------------
__global__ __launch_bounds__(256) void zero_cnt_kernel()
{
    const int i = blockIdx.x * 256 + threadIdx.x;
    if (i < N_NODES) g_cnt[i] = 0;
}

__global__ __launch_bounds__(256) void hist_kernel(const int* __restrict__ dst)
{
    const int e = blockIdx.x * 256 + threadIdx.x;
    if (e < N_EDGES) atomicAdd(&g_cnt[dst[e]], 1);
}

__global__ __launch_bounds__(256) void s1_kernel()   // per-1024-chunk sums
{
    const int b = blockIdx.x, t = threadIdx.x;
    const int base = b * 1024 + t * 4;
    int s = 0;
    #pragma unroll
    for (int j = 0; j < 4; j++) {
        const int i = base + j;
        if (i < N_NODES) s += g_cnt[i];
    }
    __shared__ int sh[256];
    sh[t] = s; __syncthreads();
    #pragma unroll
    for (int off = 128; off > 0; off >>= 1) {
        if (t < off) sh[t] += sh[t + off];
        __syncthreads();
    }
    if (t == 0) g_bsum[b] = sh[0];
}

__global__ __launch_bounds__(128) void s2_kernel()   // scan the 98 partials
{
    const int t = threadIdx.x;
    __shared__ int sh[128];
    const int v = (t < NB) ? g_bsum[t] : 0;
    sh[t] = v; __syncthreads();
    #pragma unroll
    for (int off = 1; off < 128; off <<= 1) {
        int x = 0;
        if (t >= off) x = sh[t - off];
        __syncthreads();
        sh[t] += x;
        __syncthreads();
    }
    if (t < NB) g_bsum[t] = sh[t] - v;   // exclusive
}

__global__ __launch_bounds__(256) void s3_kernel()   // chunk scan -> start/cur
{
    const int b = blockIdx.x, t = threadIdx.x;
    const int base = b * 1024 + t * 4;
    int v[4], s = 0;
    #pragma unroll
    for (int j = 0; j < 4; j++) {
        const int i = base + j;
        v[j] = (i < N_NODES) ? g_cnt[i] : 0;
        s += v[j];
    }
    __shared__ int sh[256];
    sh[t] = s; __syncthreads();
    const int own = s;
    #pragma unroll
    for (int off = 1; off < 256; off <<= 1) {
        int x = 0;
        if (t >= off) x = sh[t - off];
        __syncthreads();
        sh[t] += x;
        __syncthreads();
    }
    int ofs = g_bsum[b] + (sh[t] - own);
    #pragma unroll
    for (int j = 0; j < 4; j++) {
        const int i = base + j;
        if (i < N_NODES) { g_start[i] = ofs; g_cur[i] = ofs; }
        ofs += v[j];
    }
}

__global__ __launch_bounds__(256) void bin_kernel(
    const int* __restrict__ src, const int* __restrict__ dst)
{
    const int e = blockIdx.x * 256 + threadIdx.x;
    if (e >= N_EDGES) return;
    const int pos = atomicAdd(&g_cur[dst[e]], 1);
    g_ebuf[pos] = src[e];
}

// ---------------------------------------------------------------------------
// Gather-sum: h[n,:] = sum over edges with dst==n of v[src,:].
// Warp per node; 32 sids fetched coalesced, gathers issued in batches of 8.
// Writes every row (zeros for deg 0) -> no separate zero pass.
// ---------------------------------------------------------------------------
__global__ __launch_bounds__(256) void gather_kernel()
{
    const int n    = (int)((blockIdx.x * (unsigned)blockDim.x + threadIdx.x) >> 5);
    const int lane = threadIdx.x & 31;
    if (n >= N_NODES) return;

    const int st  = g_start[n];
    const int deg = g_cnt[n];

    float4 acc = make_float4(0.f, 0.f, 0.f, 0.f);
    for (int base = 0; base < deg; base += 32) {
        const int cm = min(32, deg - base);
        const int sid_r = (base + lane < deg) ? g_ebuf[st + base + lane] : 0;
        int j = 0;
        for (; j + 8 <= cm; j += 8) {
            float4 x[8];
            #pragma unroll
            for (int q = 0; q < 8; q++) {
                const int sid = __shfl_sync(0xffffffffu, sid_r, j + q);
                x[q] = ((const float4*)(g_v + (size_t)sid * DIM))[lane];
            }
            #pragma unroll
            for (int q = 0; q < 8; q++) {
                acc.x += x[q].x; acc.y += x[q].y;
                acc.z += x[q].z; acc.w += x[q].w;
            }
        }
        for (; j < cm; j++) {
            const int sid = __shfl_sync(0xffffffffu, sid_r, j);
            const float4 x = ((const float4*)(g_v + (size_t)sid * DIM))[lane];
            acc.x += x.x; acc.y += x.y; acc.z += x.z; acc.w += x.w;
        }
    }
    ((float4*)(g_h + (size_t)n * DIM))[lane] = acc;
}

// ---------------------------------------------------------------------------
// Persistent typed tensor-core GEMM with X prefetch pipeline: Y = X @ W[ntype]
// (unchanged from round 6 — near the SIMT mma.sync rate bound)
// ---------------------------------------------------------------------------
__global__ __launch_bounds__(256) void gemm_mma_kernel(
    const float* __restrict__ X, int mat,
    const int* __restrict__ ntype, float* __restrict__ Y, int N)
{
    extern __shared__ char dsm[];
    const uint32_t sbase = smem_u32(dsm);
    const uint32_t XH = 0, XL = 32768, WB = 65536;

    const int tid  = threadIdx.x;
    const int wid  = tid >> 5;
    const int lane = tid & 31;

    {
        const uint4* srcW0 = (const uint4*)g_Wmma[mat * 2 + 0];
        const uint4* srcW1 = (const uint4*)g_Wmma[mat * 2 + 1];
        uint4* dstW0 = (uint4*)(dsm + WB);
        uint4* dstW1 = (uint4*)(dsm + WB + 65536);
        #pragma unroll
        for (int i = 0; i < 16; i++) {
            dstW0[tid + 256 * i] = srcW0[tid + 256 * i];
            dstW1[tid + 256 * i] = srcW1[tid + 256 * i];
        }
    }

    const int m0 = (wid >> 1) * 32;
    const int n0 = (wid & 1) * 64;
    const int lrow  = tid >> 1;
    const int lkoff = (tid & 1) * 64;

    float4 pf[16];
    int tile = blockIdx.x;
    {
        const int grow = tile * 128 + lrow;
        if (tile < NTILES && grow < N) {
            const float4* xp = (const float4*)(X + (size_t)grow * DIM + lkoff);
            #pragma unroll
            for (int q = 0; q < 16; q++) pf[q] = xp[q];
        } else {
            #pragma unroll
            for (int q = 0; q < 16; q++) pf[q] = make_float4(0, 0, 0, 0);
        }
    }

    while (tile < NTILES) {
        const int row0 = tile * 128;
        const int lastRow = (row0 + 127 < N) ? (row0 + 127) : (N - 1);
        const int t0 = ntype[row0];
        const int t1 = ntype[lastRow];
        const bool mixed = (t0 != t1);
        const int ntile = tile + gridDim.x;

        __syncthreads();

        {
            const int kh = (tid & 1) * 8;
            #pragma unroll
            for (int q = 0; q < 8; q++) {
                float4 f0 = pf[2 * q], f1 = pf[2 * q + 1];
                __nv_bfloat162 h0 = __floats2bfloat162_rn(f0.x, f0.y);
                __nv_bfloat162 h1 = __floats2bfloat162_rn(f0.z, f0.w);
                __nv_bfloat162 h2 = __floats2bfloat162_rn(f1.x, f1.y);
                __nv_bfloat162 h3 = __floats2bfloat162_rn(f1.z, f1.w);
                float2 e0 = __bfloat1622float2(h0), e1 = __bfloat1622float2(h1);
                float2 e2 = __bfloat1622float2(h2), e3 = __bfloat1622float2(h3);
                __nv_bfloat162 l0 = __floats2bfloat162_rn(f0.x - e0.x, f0.y - e0.y);
                __nv_bfloat162 l1 = __floats2bfloat162_rn(f0.z - e1.x, f0.w - e1.y);
                __nv_bfloat162 l2 = __floats2bfloat162_rn(f1.x - e2.x, f1.y - e2.y);
                __nv_bfloat162 l3 = __floats2bfloat162_rn(f1.z - e3.x, f1.w - e3.y);
                const uint32_t off = SW_OFF(lrow, kh + q);
                uint4 hv, lv;
                hv.x = *(uint32_t*)&h0; hv.y = *(uint32_t*)&h1;
                hv.z = *(uint32_t*)&h2; hv.w = *(uint32_t*)&h3;
                lv.x = *(uint32_t*)&l0; lv.y = *(uint32_t*)&l1;
                lv.z = *(uint32_t*)&l2; lv.w = *(uint32_t*)&l3;
                *(uint4*)(dsm + XH + off) = hv;
                *(uint4*)(dsm + XL + off) = lv;
            }
        }

        {
            const int grow = ntile * 128 + lrow;
            if (ntile < NTILES && grow < N) {
                const float4* xp = (const float4*)(X + (size_t)grow * DIM + lkoff);
                #pragma unroll
                for (int q = 0; q < 16; q++) pf[q] = xp[q];
            } else {
                #pragma unroll
                for (int q = 0; q < 16; q++) pf[q] = make_float4(0, 0, 0, 0);
            }
        }
        __syncthreads();

        for (int t = t0; t <= t1; ++t) {
            const uint32_t bhi = sbase + WB + (uint32_t)t * 65536u;
            const uint32_t blo = bhi + 32768u;

            float acc[2][8][4];
            #pragma unroll
            for (int i = 0; i < 2; i++)
                #pragma unroll
                for (int j = 0; j < 8; j++)
                    #pragma unroll
                    for (int p = 0; p < 4; p++) acc[i][j][p] = 0.f;

            #pragma unroll
            for (int ks = 0; ks < 8; ks++) {
                uint32_t ah[2][4], al[2][4];
                {
                    const int r    = lane & 7;
                    const int half = (lane >> 3) & 1;
                    const int ksel = lane >> 4;
                    const int akc  = ks * 2 + ksel;
                    #pragma unroll
                    for (int mt = 0; mt < 2; mt++) {
                        const uint32_t aoff = SW_OFF(m0 + mt * 16 + half * 8 + r, akc);
                        ldsm_x4(ah[mt][0], ah[mt][1], ah[mt][2], ah[mt][3],
                                sbase + XH + aoff);
                        ldsm_x4(al[mt][0], al[mt][1], al[mt][2], al[mt][3],
                                sbase + XL + aoff);
                    }
                }
                uint32_t bh[8][2], bl[8][2];
                {
                    const int r    = lane & 7;
                    const int ksel = (lane >> 3) & 1;
                    const int jsel = lane >> 4;
                    const int bkc  = ks * 2 + ksel;
                    #pragma unroll
                    for (int jj = 0; jj < 4; jj++) {
                        const uint32_t boff = SW_OFF(n0 + jj * 16 + jsel * 8 + r, bkc);
                        uint32_t r0, r1, r2, r3;
                        ldsm_x4(r0, r1, r2, r3, bhi + boff);
                        bh[2 * jj][0] = r0;     bh[2 * jj][1] = r1;
                        bh[2 * jj + 1][0] = r2; bh[2 * jj + 1][1] = r3;
                        ldsm_x4(r0, r1, r2, r3, blo + boff);
                        bl[2 * jj][0] = r0;     bl[2 * jj][1] = r1;
                        bl[2 * jj + 1][0] = r2; bl[2 * jj + 1][1] = r3;
                    }
                }
                #pragma unroll
                for (int mt = 0; mt < 2; mt++)
                    #pragma unroll
                    for (int nt = 0; nt < 8; nt++) {
                        mma_bf16(acc[mt][nt], ah[mt], bh[nt]);
                        mma_bf16(acc[mt][nt], al[mt], bh[nt]);
                        mma_bf16(acc[mt][nt], ah[mt], bl[nt]);
                    }
            }

            {
                const int g  = lane >> 2;
                const int c2 = (lane & 3) * 2;
                #pragma unroll
                for (int mt = 0; mt < 2; mt++) {
                    #pragma unroll
                    for (int half = 0; half < 2; half++) {
                        const int grow = row0 + m0 + mt * 16 + half * 8 + g;
                        if (grow < N && (!mixed || ntype[grow] == t)) {
                            float2* yp = (float2*)(Y + (size_t)grow * DIM + n0 + c2);
                            #pragma unroll
                            for (int nt = 0; nt < 8; nt++)
                                yp[nt * 4] = make_float2(acc[mt][nt][half * 2],
                                                         acc[mt][nt][half * 2 + 1]);
                        }
                    }
                }
            }
        }

        tile = ntile;
    }
}

// ---------------------------------------------------------------------------
extern "C" void kernel_launch(void* const* d_in, const int* in_sizes, int n_in,
                              void* d_out, int out_size)
{
    const float* x     = (const float*)d_in[0];
    const int*   ntype = (const int*)  d_in[1];
    const int*   src   = (const int*)  d_in[2];
    const int*   dst   = (const int*)  d_in[3];
    const float* W_v   = (const float*)d_in[4];
    const float* W_a   = (const float*)d_in[5];
    float*       out   = (float*)d_out;

    float *v_ptr, *h_ptr;
    cudaGetSymbolAddress((void**)&v_ptr, g_v);
    cudaGetSymbolAddress((void**)&h_ptr, g_h);

    const int N = N_NODES;
    const int SMEM_DYN = 196608;
    cudaFuncSetAttribute(gemm_mma_kernel,
                         cudaFuncAttributeMaxDynamicSharedMemorySize, SMEM_DYN);

    // prepack W (bf16 hi/lo swizzled SMEM images)
    prepack_kernel<<<(4 * 2 * 128 * 128 + 255) / 256, 256>>>(W_v, W_a);
    // CSR-by-dst build
    zero_cnt_kernel<<<(N_NODES + 255) / 256, 256>>>();
    hist_kernel<<<(N_EDGES + 255) / 256, 256>>>(dst);
    s1_kernel<<<NB, 256>>>();
    s2_kernel<<<1, 128>>>();
    s3_kernel<<<NB, 256>>>();
    bin_kernel<<<(N_EDGES + 255) / 256, 256>>>(src, dst);
    // v = typed_linear(x, W_v, ntype)
    gemm_mma_kernel<<<148, 256, SMEM_DYN>>>(x, 0, ntype, v_ptr, N);
    // h[n] = sum_{e: dst=n} v[src[e]]
    gather_kernel<<<(N_NODES * 32 + 255) / 256, 256>>>();
    // out = typed_linear(h, W_a, ntype)
    gemm_mma_kernel<<<148, 256, SMEM_DYN>>>(h_ptr, 1, ntype, out, N);
}

// round 9
// speedup vs baseline: 1.0121x; 1.0121x over previous
#include <cuda_runtime.h>
#include <cuda_bf16.h>
#include <cstdint>

#define N_NODES 100000
#define N_EDGES 800000
#define DIM 128
#define NTILES ((N_NODES + 127) / 128)

// ---------------------------------------------------------------------------
// Scratch (allocation-free rule: __device__ globals)
// ---------------------------------------------------------------------------
__device__ float g_v[N_NODES * DIM];
__device__ float g_h[N_NODES * DIM];
__device__ unsigned short g_Wmma[4][2 * 128 * 128];  // prepacked W images

// swizzled byte offset of (row, 16B-chunk kc) in a 256B-row tile
#define SW_OFF(row, kc) ((uint32_t)(row) * 256u + ((uint32_t)(((kc) ^ ((row) & 7))) << 4))

__device__ __forceinline__ uint32_t smem_u32(const void* p) {
    uint32_t a;
    asm("{ .reg .u64 t; cvta.to.shared.u64 t, %1; cvt.u32.u64 %0, t; }"
        : "=r"(a) : "l"(p));
    return a;
}
__device__ __forceinline__ void ldsm_x4(uint32_t& r0, uint32_t& r1, uint32_t& r2,
                                        uint32_t& r3, uint32_t addr) {
    asm volatile("ldmatrix.sync.aligned.m8n8.x4.shared.b16 {%0,%1,%2,%3}, [%4];"
                 : "=r"(r0), "=r"(r1), "=r"(r2), "=r"(r3) : "r"(addr));
}
__device__ __forceinline__ void mma_bf16(float* d, const uint32_t* a, const uint32_t* b) {
    asm volatile(
        "mma.sync.aligned.m16n8k16.row.col.f32.bf16.bf16.f32 "
        "{%0,%1,%2,%3}, {%4,%5,%6,%7}, {%8,%9}, {%0,%1,%2,%3};"
        : "+f"(d[0]), "+f"(d[1]), "+f"(d[2]), "+f"(d[3])
        : "r"(a[0]), "r"(a[1]), "r"(a[2]), "r"(a[3]), "r"(b[0]), "r"(b[1]));
}

// ---------------------------------------------------------------------------
// Prepack W -> g_Wmma: bf16 hi/lo, [n][k] rows (256B), XOR-swizzled 16B chunks
// ---------------------------------------------------------------------------
__global__ __launch_bounds__(256) void prepack_kernel(
    const float* __restrict__ W_v, const float* __restrict__ W_a)
{
    const int idx = blockIdx.x * 256 + threadIdx.x;
    if (idx >= 4 * 2 * 128 * 128) return;
    const int tile = idx >> 15;
    const int seg  = (idx >> 14) & 1;
    const int rem  = idx & 16383;
    const int n    = rem >> 7;
    const int k    = rem & 127;
    const int mat  = tile >> 1;
    const int typ  = tile & 1;

    const float* Wp = (mat ? W_a : W_v) + typ * DIM * DIM;
    const float w = Wp[k * DIM + n];
    __nv_bfloat16 hi = __float2bfloat16_rn(w);
    unsigned short out;
    if (seg == 0) {
        out = *(unsigned short*)&hi;
    } else {
        __nv_bfloat16 lo = __float2bfloat16_rn(w - __bfloat162float(hi));
        out = *(unsigned short*)&lo;
    }
    const uint32_t boff = SW_OFF(n, k >> 3) + (k & 7) * 2;
    g_Wmma[tile][seg * 16384 + (boff >> 1)] = out;
}

// ---------------------------------------------------------------------------
// Persistent typed tensor-core GEMM, 512 threads (16 warps, 4/SMSP).
// Warp grid 4m x 4n, warp tile 32x32. W (both types hi/lo, 128KB) resident.
// Per tile: convert prefetched X regs -> smem, prefetch next tile (hidden
// behind MMA), 3-segment bf16 MMA (hi*hi + lo*hi + hi*lo), masked epilogue.
// ---------------------------------------------------------------------------
__global__ __launch_bounds__(512) void gemm_mma_kernel(
    const float* __restrict__ X, int mat,
    const int* __restrict__ ntype, float* __restrict__ Y, int N)
{
    extern __shared__ char dsm[];
    const uint32_t sbase = smem_u32(dsm);
    const uint32_t XH = 0, XL = 32768, WB = 65536;   // W: +type*65536 +seg*32768

    const int tid  = threadIdx.x;
    const int wid  = tid >> 5;
    const int lane = tid & 31;

    // ---- load W (both types, hi+lo = 128KB) once -------------------------
    // each image: 64KB = 4096 uint4; 512 threads x 8 iters
    {
        const uint4* srcW0 = (const uint4*)g_Wmma[mat * 2 + 0];
        const uint4* srcW1 = (const uint4*)g_Wmma[mat * 2 + 1];
        uint4* dstW0 = (uint4*)(dsm + WB);
        uint4* dstW1 = (uint4*)(dsm + WB + 65536);
        #pragma unroll
        for (int i = 0; i < 8; i++) {
            dstW0[tid + 512 * i] = srcW0[tid + 512 * i];
            dstW1[tid + 512 * i] = srcW1[tid + 512 * i];
        }
    }

    // warp tile position (4m x 4n grid of 32x32 warp tiles)
    const int m0 = (wid >> 2) * 32;
    const int n0 = (wid & 3) * 32;

    // loader mapping: row = tid>>2, k-quarter = (tid&3)*32 floats
    const int lrow  = tid >> 2;
    const int lkoff = (tid & 3) * 32;

    // ---- prologue: prefetch first tile's X slice (8 float4 = 32 floats) ---
    float4 pf[8];
    int tile = blockIdx.x;
    {
        const int grow = tile * 128 + lrow;
        if (tile < NTILES && grow < N) {
            const float4* xp = (const float4*)(X + (size_t)grow * DIM + lkoff);
            #pragma unroll
            for (int q = 0; q < 8; q++) pf[q] = xp[q];
        } else {
            #pragma unroll
            for (int q = 0; q < 8; q++) pf[q] = make_float4(0, 0, 0, 0);
        }
    }

    while (tile < NTILES) {
        const int row0 = tile * 128;
        const int lastRow = (row0 + 127 < N) ? (row0 + 127) : (N - 1);
        const int t0 = ntype[row0];
        const int t1 = ntype[lastRow];
        const bool mixed = (t0 != t1);
        const int ntile = tile + gridDim.x;

        __syncthreads();   // previous tile's compute done before X overwrite

        // ---- convert prefetched X -> bf16 hi/lo swizzled SMEM -------------
        {
            const int kh = (tid & 3) * 4;  // 16B-chunk base (4 chunks/thread)
            #pragma unroll
            for (int q = 0; q < 4; q++) {
                float4 f0 = pf[2 * q], f1 = pf[2 * q + 1];
                __nv_bfloat162 h0 = __floats2bfloat162_rn(f0.x, f0.y);
                __nv_bfloat162 h1 = __floats2bfloat162_rn(f0.z, f0.w);
                __nv_bfloat162 h2 = __floats2bfloat162_rn(f1.x, f1.y);
                __nv_bfloat162 h3 = __floats2bfloat162_rn(f1.z, f1.w);
                float2 e0 = __bfloat1622float2(h0), e1 = __bfloat1622float2(h1);
                float2 e2 = __bfloat1622float2(h2), e3 = __bfloat1622float2(h3);
                __nv_bfloat162 l0 = __floats2bfloat162_rn(f0.x - e0.x, f0.y - e0.y);
                __nv_bfloat162 l1 = __floats2bfloat162_rn(f0.z - e1.x, f0.w - e1.y);
                __nv_bfloat162 l2 = __floats2bfloat162_rn(f1.x - e2.x, f1.y - e2.y);
                __nv_bfloat162 l3 = __floats2bfloat162_rn(f1.z - e3.x, f1.w - e3.y);
                const uint32_t off = SW_OFF(lrow, kh + q);
                uint4 hv, lv;
                hv.x = *(uint32_t*)&h0; hv.y = *(uint32_t*)&h1;
                hv.z = *(uint32_t*)&h2; hv.w = *(uint32_t*)&h3;
                lv.x = *(uint32_t*)&l0; lv.y = *(uint32_t*)&l1;
                lv.z = *(uint32_t*)&l2; lv.w = *(uint32_t*)&l3;
                *(uint4*)(dsm + XH + off) = hv;
                *(uint4*)(dsm + XL + off) = lv;
            }
        }

        // ---- prefetch next tile's X (latency hidden behind MMA) ----------
        {
            const int grow = ntile * 128 + lrow;
            if (ntile < NTILES && grow < N) {
                const float4* xp = (const float4*)(X + (size_t)grow * DIM + lkoff);
                #pragma unroll
                for (int q = 0; q < 8; q++) pf[q] = xp[q];
            } else {
                #pragma unroll
                for (int q = 0; q < 8; q++) pf[q] = make_float4(0, 0, 0, 0);
            }
        }
        __syncthreads();

        for (int t = t0; t <= t1; ++t) {
            const uint32_t bhi = sbase + WB + (uint32_t)t * 65536u;
            const uint32_t blo = bhi + 32768u;

            float acc[2][4][4];
            #pragma unroll
            for (int i = 0; i < 2; i++)
                #pragma unroll
                for (int j = 0; j < 4; j++)
                    #pragma unroll
                    for (int p = 0; p < 4; p++) acc[i][j][p] = 0.f;

            #pragma unroll
            for (int ks = 0; ks < 8; ks++) {
                // ---- A fragments (hi & lo) --------------------------------
                uint32_t ah[2][4], al[2][4];
                {
                    const int r    = lane & 7;
                    const int half = (lane >> 3) & 1;
                    const int ksel = lane >> 4;
                    const int akc  = ks * 2 + ksel;
                    #pragma unroll
                    for (int mt = 0; mt < 2; mt++) {
                        const uint32_t aoff = SW_OFF(m0 + mt * 16 + half * 8 + r, akc);
                        ldsm_x4(ah[mt][0], ah[mt][1], ah[mt][2], ah[mt][3],
                                sbase + XH + aoff);
                        ldsm_x4(al[mt][0], al[mt][1], al[mt][2], al[mt][3],
                                sbase + XL + aoff);
                    }
                }
                // ---- B fragments (hi & lo), 32 cols -----------------------
                uint32_t bh[4][2], bl[4][2];
                {
                    const int r    = lane & 7;
                    const int ksel = (lane >> 3) & 1;
                    const int jsel = lane >> 4;
                    const int bkc  = ks * 2 + ksel;
                    #pragma unroll
                    for (int jj = 0; jj < 2; jj++) {
                        const uint32_t boff = SW_OFF(n0 + jj * 16 + jsel * 8 + r, bkc);
                        uint32_t r0, r1, r2, r3;
                        ldsm_x4(r0, r1, r2, r3, bhi + boff);
                        bh[2 * jj][0] = r0;     bh[2 * jj][1] = r1;
                        bh[2 * jj + 1][0] = r2; bh[2 * jj + 1][1] = r3;
                        ldsm_x4(r0, r1, r2, r3, blo + boff);
                        bl[2 * jj][0] = r0;     bl[2 * jj][1] = r1;
                        bl[2 * jj + 1][0] = r2; bl[2 * jj + 1][1] = r3;
                    }
                }
                // ---- 3 MMA combos from registers --------------------------
                #pragma unroll
                for (int mt = 0; mt < 2; mt++)
                    #pragma unroll
                    for (int nt = 0; nt < 4; nt++) {
                        mma_bf16(acc[mt][nt], ah[mt], bh[nt]);
                        mma_bf16(acc[mt][nt], al[mt], bh[nt]);
                        mma_bf16(acc[mt][nt], ah[mt], bl[nt]);
                    }
            }

            // ---- epilogue: masked writeout --------------------------------
            {
                const int g  = lane >> 2;
                const int c2 = (lane & 3) * 2;
                #pragma unroll
                for (int mt = 0; mt < 2; mt++) {
                    #pragma unroll
                    for (int half = 0; half < 2; half++) {
                        const int grow = row0 + m0 + mt * 16 + half * 8 + g;
                        if (grow < N && (!mixed || ntype[grow] == t)) {
                            float2* yp = (float2*)(Y + (size_t)grow * DIM + n0 + c2);
                            #pragma unroll
                            for (int nt = 0; nt < 4; nt++)
                                yp[nt * 4] = make_float2(acc[mt][nt][half * 2],
                                                         acc[mt][nt][half * 2 + 1]);
                        }
                    }
                }
            }
        }

        tile = ntile;
    }
}

// ---------------------------------------------------------------------------
// Edge scatter-sum: g_h[dst[e],:] += g_v[src[e],:]. 8 edges per warp:
// uniform int4 index loads, 8 independent gathers (MLP=8), 8 RED.128/lane.
// ---------------------------------------------------------------------------
__global__ __launch_bounds__(256) void scatter_kernel(
    const int* __restrict__ src, const int* __restrict__ dst)
{
    const int w    = (int)((blockIdx.x * (unsigned)blockDim.x + threadIdx.x) >> 5);
    const int lane = threadIdx.x & 31;
    const int4 s0 = __ldg((const int4*)src + w * 2);
    const int4 s1 = __ldg((const int4*)src + w * 2 + 1);
    const int4 d0 = __ldg((const int4*)dst + w * 2);
    const int4 d1 = __ldg((const int4*)dst + w * 2 + 1);
    const int s[8] = {s0.x, s0.y, s0.z, s0.w, s1.x, s1.y, s1.z, s1.w};
    const int d[8] = {d0.x, d0.y, d0.z, d0.w, d1.x, d1.y, d1.z, d1.w};

    float4 x[8];
    #pragma unroll
    for (int i = 0; i < 8; i++)
        x[i] = ((const float4*)(g_v + (size_t)s[i] * DIM))[lane];

    #pragma unroll
    for (int i = 0; i < 8; i++) {
        float* hd = g_h + (size_t)d[i] * DIM + lane * 4;
        asm volatile("red.global.add.v4.f32 [%0], {%1, %2, %3, %4};"
                     :: "l"(hd), "f"(x[i].x), "f"(x[i].y), "f"(x[i].z), "f"(x[i].w)
                     : "memory");
    }
}

// ---------------------------------------------------------------------------
__global__ __launch_bounds__(256) void zero_h_kernel()
{
    const int i = blockIdx.x * blockDim.x + threadIdx.x;
    if (i < N_NODES * DIM / 4)
        ((float4*)g_h)[i] = make_float4(0.f, 0.f, 0.f, 0.f);
}

// ---------------------------------------------------------------------------
extern "C" void kernel_launch(void* const* d_in, const int* in_sizes, int n_in,
                              void* d_out, int out_size)
{
    const float* x     = (const float*)d_in[0];
    const int*   ntype = (const int*)  d_in[1];
    const int*   src   = (const int*)  d_in[2];
    const int*   dst   = (const int*)  d_in[3];
    const float* W_v   = (const float*)d_in[4];
    const float* W_a   = (const float*)d_in[5];
    float*       out   = (float*)d_out;

    float *v_ptr, *h_ptr;
    cudaGetSymbolAddress((void**)&v_ptr, g_v);
    cudaGetSymbolAddress((void**)&h_ptr, g_h);

    const int N = N_NODES;
    const int SMEM_DYN = 196608;   // Xhi+Xlo (64K) + W both types hi/lo (128K)
    cudaFuncSetAttribute(gemm_mma_kernel,
                         cudaFuncAttributeMaxDynamicSharedMemorySize, SMEM_DYN);

    // prepack W (bf16 hi/lo swizzled SMEM images)
    prepack_kernel<<<(4 * 2 * 128 * 128 + 255) / 256, 256>>>(W_v, W_a);
    // h = 0
    zero_h_kernel<<<(N_NODES * DIM / 4 + 255) / 256, 256>>>();
    // v = typed_linear(x, W_v, ntype)
    gemm_mma_kernel<<<148, 512, SMEM_DYN>>>(x, 0, ntype, v_ptr, N);
    // h[dst] += v[src]  (8 edges/warp)
    scatter_kernel<<<N_EDGES / 8 / 8, 256>>>(src, dst);
    // out = typed_linear(h, W_a, ntype)
    gemm_mma_kernel<<<148, 512, SMEM_DYN>>>(h_ptr, 1, ntype, out, N);
}